// round 1
// baseline (speedup 1.0000x reference)
#include <cuda_runtime.h>
#include <math.h>

#define B_   2
#define T_   2048
#define C_   2048
#define NH   16
#define NKV  4
#define HD   128
#define SCALE 0.08838834764831845f  // 1/sqrt(128)

// Scratch (device globals; no allocation allowed)
__device__ float g_q[(size_t)B_ * NH  * T_ * HD];   // [B, NH, T, D]
__device__ float g_k[(size_t)B_ * NKV * T_ * HD];   // [B, NKV, T, D]
__device__ float g_v[(size_t)B_ * NKV * T_ * HD];   // [B, NKV, T, D]
__device__ float g_y[(size_t)B_ * T_ * C_];         // [B, T, C]

// ---------------------------------------------------------------------------
// SGEMM (NT): C[M,N] = A[M,K] * B[N,K]^T, fp32, row-major.
// Block tile 128x128, BK=16, 256 threads, 8x8 per-thread microtile.
// mode 0: C row-major [M,N].  mode 1: scatter to [B, Hn, T, HD].
// ---------------------------------------------------------------------------
__global__ __launch_bounds__(256) void sgemm_nt(
    const float* __restrict__ A, const float* __restrict__ Bw,
    float* __restrict__ Cout, int M, int N, int K, int mode, int Hn)
{
    __shared__ float As[16][128];
    __shared__ float Bs[16][128];

    const int tid = threadIdx.x;
    const int tx = tid & 15, ty = tid >> 4;
    const int bm = blockIdx.y, bn = blockIdx.x;

    const float* Ab = A  + (size_t)bm * 128 * K;
    const float* Bb = Bw + (size_t)bn * 128 * K;

    float acc[8][8];
    #pragma unroll
    for (int i = 0; i < 8; i++)
        #pragma unroll
        for (int j = 0; j < 8; j++) acc[i][j] = 0.f;

    for (int k0 = 0; k0 < K; k0 += 16) {
        #pragma unroll
        for (int i = 0; i < 2; i++) {
            int f4 = i * 256 + tid;            // 512 float4 per tile
            int r  = f4 >> 2;
            int c4 = (f4 & 3) << 2;
            float4 a = *(const float4*)(Ab + (size_t)r * K + k0 + c4);
            As[c4 + 0][r] = a.x; As[c4 + 1][r] = a.y;
            As[c4 + 2][r] = a.z; As[c4 + 3][r] = a.w;
            float4 b = *(const float4*)(Bb + (size_t)r * K + k0 + c4);
            Bs[c4 + 0][r] = b.x; Bs[c4 + 1][r] = b.y;
            Bs[c4 + 2][r] = b.z; Bs[c4 + 3][r] = b.w;
        }
        __syncthreads();

        #pragma unroll
        for (int kk = 0; kk < 16; kk++) {
            float ra[8], rb[8];
            *(float4*)&ra[0] = *(const float4*)&As[kk][ty * 4];
            *(float4*)&ra[4] = *(const float4*)&As[kk][64 + ty * 4];
            *(float4*)&rb[0] = *(const float4*)&Bs[kk][tx * 4];
            *(float4*)&rb[4] = *(const float4*)&Bs[kk][64 + tx * 4];
            #pragma unroll
            for (int i = 0; i < 8; i++)
                #pragma unroll
                for (int j = 0; j < 8; j++)
                    acc[i][j] = fmaf(ra[i], rb[j], acc[i][j]);
        }
        __syncthreads();
    }

    #pragma unroll
    for (int i = 0; i < 8; i++) {
        int r = bm * 128 + ((i < 4) ? (ty * 4 + i) : (64 + ty * 4 + (i - 4)));
        #pragma unroll
        for (int jg = 0; jg < 2; jg++) {
            int c = bn * 128 + (jg ? (64 + tx * 4) : (tx * 4));
            float4 v;
            v.x = acc[i][jg * 4 + 0]; v.y = acc[i][jg * 4 + 1];
            v.z = acc[i][jg * 4 + 2]; v.w = acc[i][jg * 4 + 3];
            if (mode == 0) {
                *(float4*)(Cout + (size_t)r * N + c) = v;
            } else {
                int b = r >> 11, t = r & (T_ - 1);
                int h = c >> 7,  d = c & (HD - 1);
                *(float4*)(Cout + ((((size_t)b * Hn + h) * T_ + t) * HD + d)) = v;
            }
        }
    }
}

// ---------------------------------------------------------------------------
// RoPE in-place on a [B, Hx, T, D] buffer. One thread per (bh, t, d2) pair.
// ---------------------------------------------------------------------------
__global__ void rope_kernel(float* __restrict__ buf,
                            const float* __restrict__ fcos,
                            const float* __restrict__ fsin)
{
    int idx = blockIdx.x * blockDim.x + threadIdx.x;
    int d2 = idx & 63;
    int t  = (idx >> 6) & (T_ - 1);
    float c = fcos[t * 64 + d2];
    float s = fsin[t * 64 + d2];
    float* p = buf + (size_t)idx * 2;
    float x0 = p[0], x1 = p[1];
    p[0] = x0 * c - x1 * s;
    p[1] = x0 * s + x1 * c;
}

// ---------------------------------------------------------------------------
// Causal flash attention. Grid: (T/64, B*NH). 256 threads (16x16).
// BM=BN=64, D=128. Online softmax; GQA via kvh = h >> 2.
// Smem: Qs[128][64] + Ks[128][64] + Vs[64][128] + Ps[64][64] = 112 KB (dynamic)
// ---------------------------------------------------------------------------
__global__ __launch_bounds__(256) void attn_kernel(float* __restrict__ y)
{
    extern __shared__ float sm[];
    float* Qs = sm;                    // [D][64]   (transposed)
    float* Ks = Qs + 128 * 64;         // [D][64]   (transposed)
    float* Vs = Ks + 128 * 64;         // [64][128]
    float* Ps = Vs + 64 * 128;         // [64][64]

    const int tid = threadIdx.x;
    const int tx = tid & 15, ty = tid >> 4;
    const int qt = blockIdx.x;
    const int bh = blockIdx.y;
    const int b  = bh >> 4, h = bh & 15;
    const int kvh = h >> 2;

    const float* Qg = g_q + (((size_t)(b * NH + h) * T_) + qt * 64) * HD;
    const float* Kg = g_k + ((size_t)(b * NKV + kvh) * T_) * HD;
    const float* Vg = g_v + ((size_t)(b * NKV + kvh) * T_) * HD;

    // Load Q tile transposed, scaled by 1/sqrt(D)
    #pragma unroll
    for (int i = 0; i < 8; i++) {
        int f4 = i * 256 + tid;        // 2048 float4 total
        int r  = f4 >> 5;
        int c4 = (f4 & 31) << 2;
        float4 q = *(const float4*)(Qg + (size_t)r * HD + c4);
        Qs[(c4 + 0) * 64 + r] = q.x * SCALE;
        Qs[(c4 + 1) * 64 + r] = q.y * SCALE;
        Qs[(c4 + 2) * 64 + r] = q.z * SCALE;
        Qs[(c4 + 3) * 64 + r] = q.w * SCALE;
    }

    float m_i[4], l_i[4], o[4][8];
    #pragma unroll
    for (int i = 0; i < 4; i++) {
        m_i[i] = -INFINITY; l_i[i] = 0.f;
        #pragma unroll
        for (int j = 0; j < 8; j++) o[i][j] = 0.f;
    }

    for (int kt = 0; kt <= qt; kt++) {
        __syncthreads();  // previous PV reads done (also guards first Q use)
        // Load K tile (transposed) and V tile (row-major)
        #pragma unroll
        for (int i = 0; i < 8; i++) {
            int f4 = i * 256 + tid;
            int r  = f4 >> 5;
            int c4 = (f4 & 31) << 2;
            float4 kv = *(const float4*)(Kg + (size_t)(kt * 64 + r) * HD + c4);
            Ks[(c4 + 0) * 64 + r] = kv.x;
            Ks[(c4 + 1) * 64 + r] = kv.y;
            Ks[(c4 + 2) * 64 + r] = kv.z;
            Ks[(c4 + 3) * 64 + r] = kv.w;
            float4 vv = *(const float4*)(Vg + (size_t)(kt * 64 + r) * HD + c4);
            *(float4*)&Vs[r * 128 + c4] = vv;
        }
        __syncthreads();

        // S = Q * K^T   (4x4 per thread)
        float s[4][4];
        #pragma unroll
        for (int i = 0; i < 4; i++)
            #pragma unroll
            for (int j = 0; j < 4; j++) s[i][j] = 0.f;

        for (int d = 0; d < 128; d++) {
            float4 qa = *(const float4*)&Qs[d * 64 + ty * 4];
            float4 kb = *(const float4*)&Ks[d * 64 + tx * 4];
            float qv[4] = {qa.x, qa.y, qa.z, qa.w};
            float kv[4] = {kb.x, kb.y, kb.z, kb.w};
            #pragma unroll
            for (int i = 0; i < 4; i++)
                #pragma unroll
                for (int j = 0; j < 4; j++)
                    s[i][j] = fmaf(qv[i], kv[j], s[i][j]);
        }

        // Causal mask on diagonal tile
        if (kt == qt) {
            #pragma unroll
            for (int i = 0; i < 4; i++)
                #pragma unroll
                for (int j = 0; j < 4; j++)
                    if (tx * 4 + j > ty * 4 + i) s[i][j] = -1e30f;
        }

        // Online softmax update
        float p[4][4];
        #pragma unroll
        for (int i = 0; i < 4; i++) {
            float rm = fmaxf(fmaxf(s[i][0], s[i][1]), fmaxf(s[i][2], s[i][3]));
            #pragma unroll
            for (int off = 1; off < 16; off <<= 1)
                rm = fmaxf(rm, __shfl_xor_sync(0xffffffffu, rm, off));
            float m_new = fmaxf(m_i[i], rm);
            float corr = __expf(m_i[i] - m_new);
            float rs = 0.f;
            #pragma unroll
            for (int j = 0; j < 4; j++) {
                p[i][j] = __expf(s[i][j] - m_new);
                rs += p[i][j];
            }
            #pragma unroll
            for (int off = 1; off < 16; off <<= 1)
                rs += __shfl_xor_sync(0xffffffffu, rs, off);
            l_i[i] = l_i[i] * corr + rs;
            m_i[i] = m_new;
            #pragma unroll
            for (int j = 0; j < 8; j++) o[i][j] *= corr;
            *(float4*)&Ps[(ty * 4 + i) * 64 + tx * 4] =
                make_float4(p[i][0], p[i][1], p[i][2], p[i][3]);
        }
        __syncthreads();

        // O += P * V
        for (int j = 0; j < 64; j++) {
            float4 v0 = *(const float4*)&Vs[j * 128 + tx * 4];
            float4 v1 = *(const float4*)&Vs[j * 128 + 64 + tx * 4];
            #pragma unroll
            for (int i = 0; i < 4; i++) {
                float pij = Ps[(ty * 4 + i) * 64 + j];
                o[i][0] = fmaf(pij, v0.x, o[i][0]);
                o[i][1] = fmaf(pij, v0.y, o[i][1]);
                o[i][2] = fmaf(pij, v0.z, o[i][2]);
                o[i][3] = fmaf(pij, v0.w, o[i][3]);
                o[i][4] = fmaf(pij, v1.x, o[i][4]);
                o[i][5] = fmaf(pij, v1.y, o[i][5]);
                o[i][6] = fmaf(pij, v1.z, o[i][6]);
                o[i][7] = fmaf(pij, v1.w, o[i][7]);
            }
        }
    }

    // Write y[b, t, h*D + d]
    #pragma unroll
    for (int i = 0; i < 4; i++) {
        float inv = 1.f / l_i[i];
        int row = qt * 64 + ty * 4 + i;
        float* yp = y + ((size_t)b * T_ + row) * C_ + h * HD;
        *(float4*)(yp + tx * 4) =
            make_float4(o[i][0] * inv, o[i][1] * inv, o[i][2] * inv, o[i][3] * inv);
        *(float4*)(yp + 64 + tx * 4) =
            make_float4(o[i][4] * inv, o[i][5] * inv, o[i][6] * inv, o[i][7] * inv);
    }
}

// ---------------------------------------------------------------------------
extern "C" void kernel_launch(void* const* d_in, const int* in_sizes, int n_in,
                              void* d_out, int out_size)
{
    const float* x    = (const float*)d_in[0];
    const float* fcos = (const float*)d_in[1];
    const float* fsin = (const float*)d_in[2];
    const float* wq   = (const float*)d_in[3];
    const float* wk   = (const float*)d_in[4];
    const float* wv   = (const float*)d_in[5];
    const float* wo   = (const float*)d_in[6];
    float* out = (float*)d_out;

    float *qp, *kp, *vp, *yp;
    cudaGetSymbolAddress((void**)&qp, g_q);
    cudaGetSymbolAddress((void**)&kp, g_k);
    cudaGetSymbolAddress((void**)&vp, g_v);
    cudaGetSymbolAddress((void**)&yp, g_y);

    const int M = B_ * T_;  // 4096

    // QKV projections (scatter into [B, H, T, D])
    sgemm_nt<<<dim3(C_ / 128, M / 128), 256>>>(x, wq, qp, M, C_, C_, 1, NH);
    sgemm_nt<<<dim3((NKV * HD) / 128, M / 128), 256>>>(x, wk, kp, M, NKV * HD, C_, 1, NKV);
    sgemm_nt<<<dim3((NKV * HD) / 128, M / 128), 256>>>(x, wv, vp, M, NKV * HD, C_, 1, NKV);

    // RoPE
    rope_kernel<<<(B_ * NH  * T_ * 64) / 256, 256>>>(qp, fcos, fsin);
    rope_kernel<<<(B_ * NKV * T_ * 64) / 256, 256>>>(kp, fcos, fsin);

    // Attention
    const size_t ASMEM = (size_t)(128 * 64 * 2 + 64 * 128 + 64 * 64) * sizeof(float);
    cudaFuncSetAttribute(attn_kernel, cudaFuncAttributeMaxDynamicSharedMemorySize, (int)ASMEM);
    attn_kernel<<<dim3(T_ / 64, B_ * NH), 256, ASMEM>>>(yp);

    // Output projection
    sgemm_nt<<<dim3(C_ / 128, M / 128), 256>>>(yp, wo, out, M, C_, C_, 0, 0);
}

// round 4
// speedup vs baseline: 1.4544x; 1.4544x over previous
#include <cuda_runtime.h>
#include <cuda_bf16.h>
#include <math.h>
#include <stdint.h>

#define B_   2
#define T_   2048
#define C_   2048
#define NH   16
#define NKV  4
#define HD   128
#define SCALE 0.08838834764831845f  // 1/sqrt(128)

// ---------------------------------------------------------------------------
// Scratch (device globals; no allocation allowed)
// ---------------------------------------------------------------------------
__device__ float g_q[(size_t)B_ * NH  * T_ * HD];   // [B, NH, T, D]
__device__ float g_k[(size_t)B_ * NKV * T_ * HD];
__device__ float g_v[(size_t)B_ * NKV * T_ * HD];
__device__ float g_y[(size_t)B_ * T_ * C_];

__device__ __nv_bfloat16 g_xhi[(size_t)B_ * T_ * C_];
__device__ __nv_bfloat16 g_xlo[(size_t)B_ * T_ * C_];
__device__ __nv_bfloat16 g_yhi[(size_t)B_ * T_ * C_];
__device__ __nv_bfloat16 g_ylo[(size_t)B_ * T_ * C_];
__device__ __nv_bfloat16 g_wqhi[(size_t)C_ * C_];
__device__ __nv_bfloat16 g_wqlo[(size_t)C_ * C_];
__device__ __nv_bfloat16 g_wkhi[(size_t)NKV * HD * C_];
__device__ __nv_bfloat16 g_wklo[(size_t)NKV * HD * C_];
__device__ __nv_bfloat16 g_wvhi[(size_t)NKV * HD * C_];
__device__ __nv_bfloat16 g_wvlo[(size_t)NKV * HD * C_];
__device__ __nv_bfloat16 g_wohi[(size_t)C_ * C_];
__device__ __nv_bfloat16 g_wolo[(size_t)C_ * C_];

// ---------------------------------------------------------------------------
// PTX helpers — arch-agnostic (sm_80+): mma.sync / ldmatrix / cp.async only.
// ---------------------------------------------------------------------------
__device__ __forceinline__ uint32_t smem_u32(const void* p) {
    uint32_t a;
    asm("{ .reg .u64 t; cvta.to.shared.u64 t, %1; cvt.u32.u64 %0, t; }"
        : "=r"(a) : "l"(p));
    return a;
}

__device__ __forceinline__ void cp_async16(uint32_t saddr, const void* gaddr) {
    asm volatile("cp.async.cg.shared.global [%0], [%1], 16;"
                 :: "r"(saddr), "l"(gaddr));
}
__device__ __forceinline__ void cp_commit() {
    asm volatile("cp.async.commit_group;");
}
template <int N> __device__ __forceinline__ void cp_wait() {
    asm volatile("cp.async.wait_group %0;" :: "n"(N));
}

__device__ __forceinline__ void ldsm4(uint32_t* r, uint32_t addr) {
    asm volatile("ldmatrix.sync.aligned.m8n8.x4.shared.b16 {%0,%1,%2,%3}, [%4];"
                 : "=r"(r[0]), "=r"(r[1]), "=r"(r[2]), "=r"(r[3]) : "r"(addr));
}

__device__ __forceinline__ void mma_bf16(float* c, const uint32_t* a,
                                         uint32_t b0, uint32_t b1) {
    asm volatile(
        "mma.sync.aligned.m16n8k16.row.col.f32.bf16.bf16.f32 "
        "{%0,%1,%2,%3}, {%4,%5,%6,%7}, {%8,%9}, {%0,%1,%2,%3};"
        : "+f"(c[0]), "+f"(c[1]), "+f"(c[2]), "+f"(c[3])
        : "r"(a[0]), "r"(a[1]), "r"(a[2]), "r"(a[3]), "r"(b0), "r"(b1));
}

// ---------------------------------------------------------------------------
// fp32 -> bf16 hi/lo split
// ---------------------------------------------------------------------------
__global__ void cvt_hilo(const float4* __restrict__ in,
                         __nv_bfloat162* __restrict__ hi2,
                         __nv_bfloat162* __restrict__ lo2, int n4)
{
    int i = blockIdx.x * blockDim.x + threadIdx.x;
    if (i >= n4) return;
    float4 v = in[i];
    __nv_bfloat16 h0 = __float2bfloat16(v.x);
    __nv_bfloat16 h1 = __float2bfloat16(v.y);
    __nv_bfloat16 h2 = __float2bfloat16(v.z);
    __nv_bfloat16 h3 = __float2bfloat16(v.w);
    __nv_bfloat16 l0 = __float2bfloat16(v.x - __bfloat162float(h0));
    __nv_bfloat16 l1 = __float2bfloat16(v.y - __bfloat162float(h1));
    __nv_bfloat16 l2 = __float2bfloat16(v.z - __bfloat162float(h2));
    __nv_bfloat16 l3 = __float2bfloat16(v.w - __bfloat162float(h3));
    hi2[2 * i + 0] = __nv_bfloat162(h0, h1);
    hi2[2 * i + 1] = __nv_bfloat162(h2, h3);
    lo2[2 * i + 0] = __nv_bfloat162(l0, l1);
    lo2[2 * i + 1] = __nv_bfloat162(l2, l3);
}

// ---------------------------------------------------------------------------
// mma.sync bf16-split GEMM (NT): C[M,N] = A[M,K] * W[N,K]^T, fp32 out.
// C = Ahi*Whi + Ahi*Wlo + Alo*Whi in fp32 accumulators.
// 256 threads, CTA tile 128x128, BK=32, warp tile 64x32 (2x4 warp grid).
// Smem per stage: 4 matrices x 128 rows x 80B (32 bf16 + 16B pad) = 40960B.
// Double-buffered with cp.async.
// mode 0: C row-major [M,N].  mode 1: scatter to [B, Hn, T_, HD].
// ---------------------------------------------------------------------------
#define GMAT_BYTES 10240            // 128 * 80
#define GSTAGE     40960            // 4 * GMAT_BYTES
#define GSM_TOTAL  (2 * GSTAGE)     // 81920

__global__ __launch_bounds__(256) void gemm_mma(
    const __nv_bfloat16* __restrict__ Ahi, const __nv_bfloat16* __restrict__ Alo,
    const __nv_bfloat16* __restrict__ Whi, const __nv_bfloat16* __restrict__ Wlo,
    float* __restrict__ Cout, int K, int N, int mode, int Hn)
{
    extern __shared__ char smem[];
    const int tid = threadIdx.x;
    const int lid = tid & 31, wid = tid >> 5;
    const int wm = wid & 1, wn = wid >> 1;     // warp grid 2(m) x 4(n)
    const int bm = blockIdx.y, bn = blockIdx.x;

    const __nv_bfloat16* srcs[4];
    srcs[0] = Ahi + (size_t)bm * 128 * K;
    srcs[1] = Alo + (size_t)bm * 128 * K;
    srcs[2] = Whi + (size_t)bn * 128 * K;
    srcs[3] = Wlo + (size_t)bn * 128 * K;

    float acc[4][4][4];
    #pragma unroll
    for (int mi = 0; mi < 4; mi++)
        #pragma unroll
        for (int ni = 0; ni < 4; ni++)
            #pragma unroll
            for (int e = 0; e < 4; e++) acc[mi][ni][e] = 0.f;

    const int nst = K >> 5;   // stages of BK=32

    auto load_stage = [&](int s) {
        char* base = smem + (s & 1) * GSTAGE;
        const int k0 = s << 5;
        #pragma unroll
        for (int m = 0; m < 4; m++) {
            const __nv_bfloat16* src = srcs[m] + k0;
            char* dst = base + m * GMAT_BYTES;
            #pragma unroll
            for (int j = 0; j < 2; j++) {
                int idx = j * 256 + tid;         // 512 chunks of 16B
                int row = idx >> 2;
                int c   = idx & 3;
                cp_async16(smem_u32(dst + row * 80 + c * 16),
                           src + (size_t)row * K + c * 8);
            }
        }
        cp_commit();
    };

    load_stage(0);

    for (int s = 0; s < nst; s++) {
        if (s + 1 < nst) { load_stage(s + 1); cp_wait<1>(); }
        else             { cp_wait<0>(); }
        __syncthreads();

        const uint32_t sb = smem_u32(smem + (s & 1) * GSTAGE);
        #pragma unroll
        for (int kk = 0; kk < 2; kk++) {
            uint32_t ah[4][4], al[4][4], bh[2][4], bl[2][4];
            const int arow  = wm * 64 + (lid & 15);
            const int akcol = kk * 16 + ((lid & 16) ? 8 : 0);
            #pragma unroll
            for (int mi = 0; mi < 4; mi++) {
                uint32_t addr = sb + (arow + mi * 16) * 80 + akcol * 2;
                ldsm4(ah[mi], addr);
                ldsm4(al[mi], addr + GMAT_BYTES);
            }
            const int brow  = wn * 32 + (lid & 7) + ((lid & 16) ? 8 : 0);
            const int bkcol = kk * 16 + ((lid & 8) ? 8 : 0);
            #pragma unroll
            for (int p = 0; p < 2; p++) {
                uint32_t addr = sb + 2 * GMAT_BYTES + (brow + p * 16) * 80 + bkcol * 2;
                ldsm4(bh[p], addr);
                ldsm4(bl[p], addr + GMAT_BYTES);
            }
            #pragma unroll
            for (int mi = 0; mi < 4; mi++)
                #pragma unroll
                for (int ni = 0; ni < 4; ni++) {
                    const int p = ni >> 1, q = (ni & 1) * 2;
                    mma_bf16(acc[mi][ni], ah[mi], bh[p][q], bh[p][q + 1]);
                    mma_bf16(acc[mi][ni], ah[mi], bl[p][q], bl[p][q + 1]);
                    mma_bf16(acc[mi][ni], al[mi], bh[p][q], bh[p][q + 1]);
                }
        }
        __syncthreads();
    }

    // Epilogue: thread t of warp holds rows r, r+8 and cols 2c,2c+1 per tile
    const int r0c = lid >> 2, cc = (lid & 3) * 2;
    #pragma unroll
    for (int mi = 0; mi < 4; mi++) {
        #pragma unroll
        for (int ni = 0; ni < 4; ni++) {
            int row = bm * 128 + wm * 64 + mi * 16 + r0c;
            int col = bn * 128 + wn * 32 + ni * 8 + cc;
            #pragma unroll
            for (int half = 0; half < 2; half++) {
                int rr = row + half * 8;
                float2 v = make_float2(acc[mi][ni][half * 2], acc[mi][ni][half * 2 + 1]);
                if (mode == 0) {
                    *(float2*)(Cout + (size_t)rr * N + col) = v;
                } else {
                    int b = rr >> 11, t = rr & (T_ - 1);
                    int h = col >> 7, d = col & (HD - 1);
                    *(float2*)(Cout + ((((size_t)b * Hn + h) * T_ + t) * HD + d)) = v;
                }
            }
        }
    }
}

// ---------------------------------------------------------------------------
// RoPE in-place on a [B, Hx, T, D] buffer.
// ---------------------------------------------------------------------------
__global__ void rope_kernel(float* __restrict__ buf,
                            const float* __restrict__ fcos,
                            const float* __restrict__ fsin)
{
    int idx = blockIdx.x * blockDim.x + threadIdx.x;
    int d2 = idx & 63;
    int t  = (idx >> 6) & (T_ - 1);
    float c = fcos[t * 64 + d2];
    float s = fsin[t * 64 + d2];
    float* p = buf + (size_t)idx * 2;
    float x0 = p[0], x1 = p[1];
    p[0] = x0 * c - x1 * s;
    p[1] = x0 * s + x1 * c;
}

// ---------------------------------------------------------------------------
// Causal flash attention (scalar fp32, known-good from R1).
// ---------------------------------------------------------------------------
__global__ __launch_bounds__(256) void attn_kernel(float* __restrict__ y)
{
    extern __shared__ float sm[];
    float* Qs = sm;
    float* Ks = Qs + 128 * 64;
    float* Vs = Ks + 128 * 64;
    float* Ps = Vs + 64 * 128;

    const int tid = threadIdx.x;
    const int tx = tid & 15, ty = tid >> 4;
    const int qt = blockIdx.x;
    const int bh = blockIdx.y;
    const int b  = bh >> 4, h = bh & 15;
    const int kvh = h >> 2;

    const float* Qg = g_q + (((size_t)(b * NH + h) * T_) + qt * 64) * HD;
    const float* Kg = g_k + ((size_t)(b * NKV + kvh) * T_) * HD;
    const float* Vg = g_v + ((size_t)(b * NKV + kvh) * T_) * HD;

    #pragma unroll
    for (int i = 0; i < 8; i++) {
        int f4 = i * 256 + tid;
        int r  = f4 >> 5;
        int c4 = (f4 & 31) << 2;
        float4 q = *(const float4*)(Qg + (size_t)r * HD + c4);
        Qs[(c4 + 0) * 64 + r] = q.x * SCALE;
        Qs[(c4 + 1) * 64 + r] = q.y * SCALE;
        Qs[(c4 + 2) * 64 + r] = q.z * SCALE;
        Qs[(c4 + 3) * 64 + r] = q.w * SCALE;
    }

    float m_i[4], l_i[4], o[4][8];
    #pragma unroll
    for (int i = 0; i < 4; i++) {
        m_i[i] = -INFINITY; l_i[i] = 0.f;
        #pragma unroll
        for (int j = 0; j < 8; j++) o[i][j] = 0.f;
    }

    for (int kt = 0; kt <= qt; kt++) {
        __syncthreads();
        #pragma unroll
        for (int i = 0; i < 8; i++) {
            int f4 = i * 256 + tid;
            int r  = f4 >> 5;
            int c4 = (f4 & 31) << 2;
            float4 kv = *(const float4*)(Kg + (size_t)(kt * 64 + r) * HD + c4);
            Ks[(c4 + 0) * 64 + r] = kv.x;
            Ks[(c4 + 1) * 64 + r] = kv.y;
            Ks[(c4 + 2) * 64 + r] = kv.z;
            Ks[(c4 + 3) * 64 + r] = kv.w;
            float4 vv = *(const float4*)(Vg + (size_t)(kt * 64 + r) * HD + c4);
            *(float4*)&Vs[r * 128 + c4] = vv;
        }
        __syncthreads();

        float s[4][4];
        #pragma unroll
        for (int i = 0; i < 4; i++)
            #pragma unroll
            for (int j = 0; j < 4; j++) s[i][j] = 0.f;

        for (int d = 0; d < 128; d++) {
            float4 qa = *(const float4*)&Qs[d * 64 + ty * 4];
            float4 kb = *(const float4*)&Ks[d * 64 + tx * 4];
            float qv[4] = {qa.x, qa.y, qa.z, qa.w};
            float kv[4] = {kb.x, kb.y, kb.z, kb.w};
            #pragma unroll
            for (int i = 0; i < 4; i++)
                #pragma unroll
                for (int j = 0; j < 4; j++)
                    s[i][j] = fmaf(qv[i], kv[j], s[i][j]);
        }

        if (kt == qt) {
            #pragma unroll
            for (int i = 0; i < 4; i++)
                #pragma unroll
                for (int j = 0; j < 4; j++)
                    if (tx * 4 + j > ty * 4 + i) s[i][j] = -1e30f;
        }

        float p[4][4];
        #pragma unroll
        for (int i = 0; i < 4; i++) {
            float rm = fmaxf(fmaxf(s[i][0], s[i][1]), fmaxf(s[i][2], s[i][3]));
            #pragma unroll
            for (int off = 1; off < 16; off <<= 1)
                rm = fmaxf(rm, __shfl_xor_sync(0xffffffffu, rm, off));
            float m_new = fmaxf(m_i[i], rm);
            float corr = __expf(m_i[i] - m_new);
            float rs = 0.f;
            #pragma unroll
            for (int j = 0; j < 4; j++) {
                p[i][j] = __expf(s[i][j] - m_new);
                rs += p[i][j];
            }
            #pragma unroll
            for (int off = 1; off < 16; off <<= 1)
                rs += __shfl_xor_sync(0xffffffffu, rs, off);
            l_i[i] = l_i[i] * corr + rs;
            m_i[i] = m_new;
            #pragma unroll
            for (int j = 0; j < 8; j++) o[i][j] *= corr;
            *(float4*)&Ps[(ty * 4 + i) * 64 + tx * 4] =
                make_float4(p[i][0], p[i][1], p[i][2], p[i][3]);
        }
        __syncthreads();

        for (int j = 0; j < 64; j++) {
            float4 v0 = *(const float4*)&Vs[j * 128 + tx * 4];
            float4 v1 = *(const float4*)&Vs[j * 128 + 64 + tx * 4];
            #pragma unroll
            for (int i = 0; i < 4; i++) {
                float pij = Ps[(ty * 4 + i) * 64 + j];
                o[i][0] = fmaf(pij, v0.x, o[i][0]);
                o[i][1] = fmaf(pij, v0.y, o[i][1]);
                o[i][2] = fmaf(pij, v0.z, o[i][2]);
                o[i][3] = fmaf(pij, v0.w, o[i][3]);
                o[i][4] = fmaf(pij, v1.x, o[i][4]);
                o[i][5] = fmaf(pij, v1.y, o[i][5]);
                o[i][6] = fmaf(pij, v1.z, o[i][6]);
                o[i][7] = fmaf(pij, v1.w, o[i][7]);
            }
        }
    }

    #pragma unroll
    for (int i = 0; i < 4; i++) {
        float inv = 1.f / l_i[i];
        int row = qt * 64 + ty * 4 + i;
        float* yp = y + ((size_t)b * T_ + row) * C_ + h * HD;
        *(float4*)(yp + tx * 4) =
            make_float4(o[i][0] * inv, o[i][1] * inv, o[i][2] * inv, o[i][3] * inv);
        *(float4*)(yp + 64 + tx * 4) =
            make_float4(o[i][4] * inv, o[i][5] * inv, o[i][6] * inv, o[i][7] * inv);
    }
}

// ---------------------------------------------------------------------------
extern "C" void kernel_launch(void* const* d_in, const int* in_sizes, int n_in,
                              void* d_out, int out_size)
{
    const float* x    = (const float*)d_in[0];
    const float* fcos = (const float*)d_in[1];
    const float* fsin = (const float*)d_in[2];
    const float* wq   = (const float*)d_in[3];
    const float* wk   = (const float*)d_in[4];
    const float* wv   = (const float*)d_in[5];
    const float* wo   = (const float*)d_in[6];
    float* out = (float*)d_out;

    float *qp, *kp, *vp, *yp;
    cudaGetSymbolAddress((void**)&qp, g_q);
    cudaGetSymbolAddress((void**)&kp, g_k);
    cudaGetSymbolAddress((void**)&vp, g_v);
    cudaGetSymbolAddress((void**)&yp, g_y);

    __nv_bfloat16 *xhi, *xlo, *yhi, *ylo, *wqhi, *wqlo, *wkhi, *wklo, *wvhi, *wvlo, *wohi, *wolo;
    cudaGetSymbolAddress((void**)&xhi, g_xhi);   cudaGetSymbolAddress((void**)&xlo, g_xlo);
    cudaGetSymbolAddress((void**)&yhi, g_yhi);   cudaGetSymbolAddress((void**)&ylo, g_ylo);
    cudaGetSymbolAddress((void**)&wqhi, g_wqhi); cudaGetSymbolAddress((void**)&wqlo, g_wqlo);
    cudaGetSymbolAddress((void**)&wkhi, g_wkhi); cudaGetSymbolAddress((void**)&wklo, g_wklo);
    cudaGetSymbolAddress((void**)&wvhi, g_wvhi); cudaGetSymbolAddress((void**)&wvlo, g_wvlo);
    cudaGetSymbolAddress((void**)&wohi, g_wohi); cudaGetSymbolAddress((void**)&wolo, g_wolo);

    const int M = B_ * T_;  // 4096

    // fp32 -> bf16 hi/lo splits
    {
        int n4;
        n4 = (M * C_) / 4;
        cvt_hilo<<<(n4 + 255) / 256, 256>>>((const float4*)x, (__nv_bfloat162*)xhi, (__nv_bfloat162*)xlo, n4);
        n4 = (C_ * C_) / 4;
        cvt_hilo<<<(n4 + 255) / 256, 256>>>((const float4*)wq, (__nv_bfloat162*)wqhi, (__nv_bfloat162*)wqlo, n4);
        cvt_hilo<<<(n4 + 255) / 256, 256>>>((const float4*)wo, (__nv_bfloat162*)wohi, (__nv_bfloat162*)wolo, n4);
        n4 = (NKV * HD * C_) / 4;
        cvt_hilo<<<(n4 + 255) / 256, 256>>>((const float4*)wk, (__nv_bfloat162*)wkhi, (__nv_bfloat162*)wklo, n4);
        cvt_hilo<<<(n4 + 255) / 256, 256>>>((const float4*)wv, (__nv_bfloat162*)wvhi, (__nv_bfloat162*)wvlo, n4);
    }

    cudaFuncSetAttribute(gemm_mma, cudaFuncAttributeMaxDynamicSharedMemorySize, GSM_TOTAL);

    // QKV projections (scatter into [B, H, T, D])
    gemm_mma<<<dim3(C_ / 128, M / 128), 256, GSM_TOTAL>>>(xhi, xlo, wqhi, wqlo, qp, C_, C_, 1, NH);
    gemm_mma<<<dim3((NKV * HD) / 128, M / 128), 256, GSM_TOTAL>>>(xhi, xlo, wkhi, wklo, kp, C_, NKV * HD, 1, NKV);
    gemm_mma<<<dim3((NKV * HD) / 128, M / 128), 256, GSM_TOTAL>>>(xhi, xlo, wvhi, wvlo, vp, C_, NKV * HD, 1, NKV);

    // RoPE
    rope_kernel<<<(B_ * NH  * T_ * 64) / 256, 256>>>(qp, fcos, fsin);
    rope_kernel<<<(B_ * NKV * T_ * 64) / 256, 256>>>(kp, fcos, fsin);

    // Attention (fp32 scalar)
    const size_t ASMEM = (size_t)(128 * 64 * 2 + 64 * 128 + 64 * 64) * sizeof(float);
    cudaFuncSetAttribute(attn_kernel, cudaFuncAttributeMaxDynamicSharedMemorySize, (int)ASMEM);
    attn_kernel<<<dim3(T_ / 64, B_ * NH), 256, ASMEM>>>(yp);

    // Output projection: convert y then tensor-core GEMM
    {
        int n4 = (M * C_) / 4;
        cvt_hilo<<<(n4 + 255) / 256, 256>>>((const float4*)yp, (__nv_bfloat162*)yhi, (__nv_bfloat162*)ylo, n4);
    }
    gemm_mma<<<dim3(C_ / 128, M / 128), 256, GSM_TOTAL>>>(yhi, ylo, wohi, wolo, out, C_, C_, 0, 0);
}

// round 5
// speedup vs baseline: 3.0117x; 2.0708x over previous
#include <cuda_runtime.h>
#include <cuda_bf16.h>
#include <math.h>
#include <stdint.h>

#define B_   2
#define T_   2048
#define C_   2048
#define NH   16
#define NKV  4
#define HD   128
#define SCALE 0.08838834764831845f           // 1/sqrt(128)
#define QSCL  0.1275495818259719f            // SCALE * log2(e)

// ---------------------------------------------------------------------------
// Scratch (device globals; no allocation allowed)
// ---------------------------------------------------------------------------
__device__ float g_q[(size_t)B_ * NH  * T_ * HD];   // [B, NH, T, D] fp32
__device__ float g_k[(size_t)B_ * NKV * T_ * HD];
__device__ float g_v[(size_t)B_ * NKV * T_ * HD];

__device__ __nv_bfloat16 g_xhi[(size_t)B_ * T_ * C_];
__device__ __nv_bfloat16 g_xlo[(size_t)B_ * T_ * C_];
__device__ __nv_bfloat16 g_yhi[(size_t)B_ * T_ * C_];
__device__ __nv_bfloat16 g_ylo[(size_t)B_ * T_ * C_];
__device__ __nv_bfloat16 g_qhi[(size_t)B_ * NH  * T_ * HD];
__device__ __nv_bfloat16 g_qlo[(size_t)B_ * NH  * T_ * HD];
__device__ __nv_bfloat16 g_khi[(size_t)B_ * NKV * T_ * HD];
__device__ __nv_bfloat16 g_klo[(size_t)B_ * NKV * T_ * HD];
__device__ __nv_bfloat16 g_vhi[(size_t)B_ * NKV * T_ * HD];
__device__ __nv_bfloat16 g_vlo[(size_t)B_ * NKV * T_ * HD];
__device__ __nv_bfloat16 g_wqhi[(size_t)C_ * C_];
__device__ __nv_bfloat16 g_wqlo[(size_t)C_ * C_];
__device__ __nv_bfloat16 g_wkhi[(size_t)NKV * HD * C_];
__device__ __nv_bfloat16 g_wklo[(size_t)NKV * HD * C_];
__device__ __nv_bfloat16 g_wvhi[(size_t)NKV * HD * C_];
__device__ __nv_bfloat16 g_wvlo[(size_t)NKV * HD * C_];
__device__ __nv_bfloat16 g_wohi[(size_t)C_ * C_];
__device__ __nv_bfloat16 g_wolo[(size_t)C_ * C_];

// ---------------------------------------------------------------------------
// PTX helpers — arch-agnostic (sm_80+)
// ---------------------------------------------------------------------------
__device__ __forceinline__ uint32_t smem_u32(const void* p) {
    uint32_t a;
    asm("{ .reg .u64 t; cvta.to.shared.u64 t, %1; cvt.u32.u64 %0, t; }"
        : "=r"(a) : "l"(p));
    return a;
}
__device__ __forceinline__ void cp_async16(uint32_t saddr, const void* gaddr) {
    asm volatile("cp.async.cg.shared.global [%0], [%1], 16;"
                 :: "r"(saddr), "l"(gaddr));
}
__device__ __forceinline__ void cp_commit() { asm volatile("cp.async.commit_group;"); }
template <int N> __device__ __forceinline__ void cp_wait() {
    asm volatile("cp.async.wait_group %0;" :: "n"(N));
}
__device__ __forceinline__ void ldsm4(uint32_t* r, uint32_t addr) {
    asm volatile("ldmatrix.sync.aligned.m8n8.x4.shared.b16 {%0,%1,%2,%3}, [%4];"
                 : "=r"(r[0]), "=r"(r[1]), "=r"(r[2]), "=r"(r[3]) : "r"(addr));
}
__device__ __forceinline__ void ldsm4t(uint32_t* r, uint32_t addr) {
    asm volatile("ldmatrix.sync.aligned.m8n8.x4.trans.shared.b16 {%0,%1,%2,%3}, [%4];"
                 : "=r"(r[0]), "=r"(r[1]), "=r"(r[2]), "=r"(r[3]) : "r"(addr));
}
__device__ __forceinline__ void mma_bf16(float* c, const uint32_t* a,
                                         uint32_t b0, uint32_t b1) {
    asm volatile(
        "mma.sync.aligned.m16n8k16.row.col.f32.bf16.bf16.f32 "
        "{%0,%1,%2,%3}, {%4,%5,%6,%7}, {%8,%9}, {%0,%1,%2,%3};"
        : "+f"(c[0]), "+f"(c[1]), "+f"(c[2]), "+f"(c[3])
        : "r"(a[0]), "r"(a[1]), "r"(a[2]), "r"(a[3]), "r"(b0), "r"(b1));
}
__device__ __forceinline__ float ex2f(float x) {
    float y; asm("ex2.approx.f32 %0, %1;" : "=f"(y) : "f"(x)); return y;
}
__device__ __forceinline__ void pack_hilo(float x, float y, uint32_t& hi, uint32_t& lo) {
    __nv_bfloat16 hx = __float2bfloat16(x), hy = __float2bfloat16(y);
    __nv_bfloat16 lx = __float2bfloat16(x - __bfloat162float(hx));
    __nv_bfloat16 ly = __float2bfloat16(y - __bfloat162float(hy));
    __nv_bfloat162 h2(hx, hy), l2(lx, ly);
    hi = *reinterpret_cast<uint32_t*>(&h2);
    lo = *reinterpret_cast<uint32_t*>(&l2);
}

// ---------------------------------------------------------------------------
// fp32 -> bf16 hi/lo split
// ---------------------------------------------------------------------------
__global__ void cvt_hilo(const float4* __restrict__ in,
                         __nv_bfloat162* __restrict__ hi2,
                         __nv_bfloat162* __restrict__ lo2, int n4)
{
    int i = blockIdx.x * blockDim.x + threadIdx.x;
    if (i >= n4) return;
    float4 v = in[i];
    uint32_t h0, l0, h1, l1;
    pack_hilo(v.x, v.y, h0, l0);
    pack_hilo(v.z, v.w, h1, l1);
    hi2[2 * i + 0] = *reinterpret_cast<__nv_bfloat162*>(&h0);
    hi2[2 * i + 1] = *reinterpret_cast<__nv_bfloat162*>(&h1);
    lo2[2 * i + 0] = *reinterpret_cast<__nv_bfloat162*>(&l0);
    lo2[2 * i + 1] = *reinterpret_cast<__nv_bfloat162*>(&l1);
}

// ---------------------------------------------------------------------------
// RoPE on fp32 [B,Hx,T,D] input -> bf16 hi/lo outputs (optionally scaled).
// ---------------------------------------------------------------------------
__global__ void rope_hilo(const float* __restrict__ buf,
                          const float* __restrict__ fcos,
                          const float* __restrict__ fsin,
                          __nv_bfloat162* __restrict__ hi2,
                          __nv_bfloat162* __restrict__ lo2, float scl)
{
    int idx = blockIdx.x * blockDim.x + threadIdx.x;
    int d2 = idx & 63;
    int t  = (idx >> 6) & (T_ - 1);
    float c = fcos[t * 64 + d2];
    float s = fsin[t * 64 + d2];
    const float* p = buf + (size_t)idx * 2;
    float x0 = p[0], x1 = p[1];
    float r0 = (x0 * c - x1 * s) * scl;
    float r1 = (x0 * s + x1 * c) * scl;
    uint32_t h, l;
    pack_hilo(r0, r1, h, l);
    hi2[idx] = *reinterpret_cast<__nv_bfloat162*>(&h);
    lo2[idx] = *reinterpret_cast<__nv_bfloat162*>(&l);
}

// ---------------------------------------------------------------------------
// mma.sync bf16-split GEMM (NT) — unchanged from R4 (passing).
// ---------------------------------------------------------------------------
#define GMAT_BYTES 10240
#define GSTAGE     40960
#define GSM_TOTAL  (2 * GSTAGE)

__global__ __launch_bounds__(256) void gemm_mma(
    const __nv_bfloat16* __restrict__ Ahi, const __nv_bfloat16* __restrict__ Alo,
    const __nv_bfloat16* __restrict__ Whi, const __nv_bfloat16* __restrict__ Wlo,
    float* __restrict__ Cout, int K, int N, int mode, int Hn)
{
    extern __shared__ char smem[];
    const int tid = threadIdx.x;
    const int lid = tid & 31, wid = tid >> 5;
    const int wm = wid & 1, wn = wid >> 1;
    const int bm = blockIdx.y, bn = blockIdx.x;

    const __nv_bfloat16* srcs[4];
    srcs[0] = Ahi + (size_t)bm * 128 * K;
    srcs[1] = Alo + (size_t)bm * 128 * K;
    srcs[2] = Whi + (size_t)bn * 128 * K;
    srcs[3] = Wlo + (size_t)bn * 128 * K;

    float acc[4][4][4];
    #pragma unroll
    for (int mi = 0; mi < 4; mi++)
        #pragma unroll
        for (int ni = 0; ni < 4; ni++)
            #pragma unroll
            for (int e = 0; e < 4; e++) acc[mi][ni][e] = 0.f;

    const int nst = K >> 5;

    auto load_stage = [&](int s) {
        char* base = smem + (s & 1) * GSTAGE;
        const int k0 = s << 5;
        #pragma unroll
        for (int m = 0; m < 4; m++) {
            const __nv_bfloat16* src = srcs[m] + k0;
            char* dst = base + m * GMAT_BYTES;
            #pragma unroll
            for (int j = 0; j < 2; j++) {
                int idx = j * 256 + tid;
                int row = idx >> 2;
                int c   = idx & 3;
                cp_async16(smem_u32(dst + row * 80 + c * 16),
                           src + (size_t)row * K + c * 8);
            }
        }
        cp_commit();
    };

    load_stage(0);

    for (int s = 0; s < nst; s++) {
        if (s + 1 < nst) { load_stage(s + 1); cp_wait<1>(); }
        else             { cp_wait<0>(); }
        __syncthreads();

        const uint32_t sb = smem_u32(smem + (s & 1) * GSTAGE);
        #pragma unroll
        for (int kk = 0; kk < 2; kk++) {
            uint32_t ah[4][4], al[4][4], bh[2][4], bl[2][4];
            const int arow  = wm * 64 + (lid & 15);
            const int akcol = kk * 16 + ((lid & 16) ? 8 : 0);
            #pragma unroll
            for (int mi = 0; mi < 4; mi++) {
                uint32_t addr = sb + (arow + mi * 16) * 80 + akcol * 2;
                ldsm4(ah[mi], addr);
                ldsm4(al[mi], addr + GMAT_BYTES);
            }
            const int brow  = wn * 32 + (lid & 7) + ((lid & 16) ? 8 : 0);
            const int bkcol = kk * 16 + ((lid & 8) ? 8 : 0);
            #pragma unroll
            for (int p = 0; p < 2; p++) {
                uint32_t addr = sb + 2 * GMAT_BYTES + (brow + p * 16) * 80 + bkcol * 2;
                ldsm4(bh[p], addr);
                ldsm4(bl[p], addr + GMAT_BYTES);
            }
            #pragma unroll
            for (int mi = 0; mi < 4; mi++)
                #pragma unroll
                for (int ni = 0; ni < 4; ni++) {
                    const int p = ni >> 1, q = (ni & 1) * 2;
                    mma_bf16(acc[mi][ni], ah[mi], bh[p][q], bh[p][q + 1]);
                    mma_bf16(acc[mi][ni], ah[mi], bl[p][q], bl[p][q + 1]);
                    mma_bf16(acc[mi][ni], al[mi], bh[p][q], bh[p][q + 1]);
                }
        }
        __syncthreads();
    }

    const int r0c = lid >> 2, cc = (lid & 3) * 2;
    #pragma unroll
    for (int mi = 0; mi < 4; mi++) {
        #pragma unroll
        for (int ni = 0; ni < 4; ni++) {
            int row = bm * 128 + wm * 64 + mi * 16 + r0c;
            int col = bn * 128 + wn * 32 + ni * 8 + cc;
            #pragma unroll
            for (int half = 0; half < 2; half++) {
                int rr = row + half * 8;
                float2 v = make_float2(acc[mi][ni][half * 2], acc[mi][ni][half * 2 + 1]);
                if (mode == 0) {
                    *(float2*)(Cout + (size_t)rr * N + col) = v;
                } else {
                    int b = rr >> 11, t = rr & (T_ - 1);
                    int h = col >> 7, d = col & (HD - 1);
                    *(float2*)(Cout + ((((size_t)b * Hn + h) * T_ + t) * HD + d)) = v;
                }
            }
        }
    }
}

// ---------------------------------------------------------------------------
// Tensor-core causal flash attention.
// CTA = (b, h, 128-row q tile). 8 warps x 16 q-rows. kv tiles of 64,
// double-buffered cp.async. hi/lo split on Q,K and P,V (3-term mma each).
// Q pre-scaled by SCALE*log2e, softmax via ex2.approx.
// Smem rows padded to 272B (128 bf16 + 16B) for conflict-free ldmatrix.
// ---------------------------------------------------------------------------
#define AROWB  272
#define AQMAT  34816                 // 128 * 272
#define AKVMAT 17408                 // 64 * 272
#define AKVST  (4 * AKVMAT)          // khi,klo,vhi,vlo = 69632
#define ASM_TOTAL (2 * AQMAT + 2 * AKVST)   // 208896

__global__ __launch_bounds__(256, 1) void attn_mma(
    const __nv_bfloat16* __restrict__ Qhi, const __nv_bfloat16* __restrict__ Qlo,
    const __nv_bfloat16* __restrict__ Khi, const __nv_bfloat16* __restrict__ Klo,
    const __nv_bfloat16* __restrict__ Vhi, const __nv_bfloat16* __restrict__ Vlo,
    __nv_bfloat16* __restrict__ Yhi, __nv_bfloat16* __restrict__ Ylo)
{
    extern __shared__ char smem[];
    const int tid = threadIdx.x;
    const int lid = tid & 31, wid = tid >> 5;
    const int qt = (T_ / 128 - 1) - blockIdx.x;       // heavy tiles first
    const int bh = blockIdx.y;
    const int b  = bh >> 4, h = bh & 15;
    const int kvh = h >> 2;

    const size_t qg = ((size_t)(b * NH + h) * T_ + qt * 128) * HD;
    const size_t kg = (size_t)(b * NKV + kvh) * T_ * HD;

    const uint32_t sQhi = smem_u32(smem);
    const uint32_t sQlo = sQhi + AQMAT;
    const uint32_t sKV0 = sQlo + AQMAT;

    // ---- load Q (both mats) + KV stage 0
    {
        #pragma unroll
        for (int i = 0; i < 16; i++) {
            int idx = i * 256 + tid;            // 4096 chunks
            int mat = idx >> 11;
            int rem = idx & 2047;
            int row = rem >> 4, c = rem & 15;
            const __nv_bfloat16* src = (mat ? Qlo : Qhi) + qg + (size_t)row * HD + c * 8;
            cp_async16((mat ? sQlo : sQhi) + row * AROWB + c * 16, src);
        }
    }
    const __nv_bfloat16* kvsrc[4] = {Khi, Klo, Vhi, Vlo};
    auto load_kv = [&](int kt, int st) {
        uint32_t sb = sKV0 + st * AKVST;
        const size_t base = kg + (size_t)kt * 64 * HD;
        #pragma unroll
        for (int i = 0; i < 16; i++) {
            int idx = i * 256 + tid;            // 4096 chunks
            int mat = idx >> 10;
            int rem = idx & 1023;
            int row = rem >> 4, c = rem & 15;
            cp_async16(sb + mat * AKVMAT + row * AROWB + c * 16,
                       kvsrc[mat] + base + (size_t)row * HD + c * 8);
        }
        cp_commit();
    };
    load_kv(0, 0);

    float oacc[16][4];
    #pragma unroll
    for (int jn = 0; jn < 16; jn++)
        #pragma unroll
        for (int e = 0; e < 4; e++) oacc[jn][e] = 0.f;
    float mrow[2] = {-1e30f, -1e30f};
    float lrow[2] = {0.f, 0.f};

    const int nkt = 2 * qt + 2;

    for (int kt = 0; kt < nkt; kt++) {
        if (kt + 1 < nkt) { load_kv(kt + 1, (kt + 1) & 1); cp_wait<1>(); }
        else              { cp_wait<0>(); }
        __syncthreads();

        const uint32_t sb  = sKV0 + (kt & 1) * AKVST;
        const uint32_t sKh = sb, sKl = sb + AKVMAT;
        const uint32_t sVh = sb + 2 * AKVMAT, sVl = sb + 3 * AKVMAT;

        // ---- S = Q K^T (3-term)
        float sacc[8][4];
        #pragma unroll
        for (int j = 0; j < 8; j++)
            #pragma unroll
            for (int e = 0; e < 4; e++) sacc[j][e] = 0.f;

        #pragma unroll
        for (int kk = 0; kk < 8; kk++) {
            uint32_t ah[4], al[4];
            const int arow  = wid * 16 + (lid & 15);
            const int akcol = kk * 16 + ((lid & 16) ? 8 : 0);
            uint32_t qaddr = sQhi + arow * AROWB + akcol * 2;
            ldsm4(ah, qaddr);
            ldsm4(al, qaddr + AQMAT);
            #pragma unroll
            for (int np = 0; np < 4; np++) {
                uint32_t bh4[4], bl4[4];
                const int brow  = np * 16 + (lid & 7) + ((lid & 16) ? 8 : 0);
                const int bkcol = kk * 16 + ((lid & 8) ? 8 : 0);
                uint32_t kaddr = brow * AROWB + bkcol * 2;
                ldsm4(bh4, sKh + kaddr);
                ldsm4(bl4, sKl + kaddr);
                #pragma unroll
                for (int jj = 0; jj < 2; jj++) {
                    const int j = 2 * np + jj, q = jj * 2;
                    mma_bf16(sacc[j], ah, bh4[q], bh4[q + 1]);
                    mma_bf16(sacc[j], ah, bl4[q], bl4[q + 1]);
                    mma_bf16(sacc[j], al, bh4[q], bh4[q + 1]);
                }
            }
        }

        // ---- causal mask (diagonal tiles only)
        const int kv0 = kt * 64;
        if (kv0 + 63 > qt * 128) {
            const int rbase = qt * 128 + wid * 16 + (lid >> 2);
            #pragma unroll
            for (int j = 0; j < 8; j++)
                #pragma unroll
                for (int e = 0; e < 4; e++) {
                    int col = kv0 + j * 8 + 2 * (lid & 3) + (e & 1);
                    int row = rbase + (e >> 1) * 8;
                    if (col > row) sacc[j][e] = -1e30f;
                }
        }

        // ---- online softmax (base-2; scale folded into Q)
        #pragma unroll
        for (int h2 = 0; h2 < 2; h2++) {
            float tm = -1e30f;
            #pragma unroll
            for (int j = 0; j < 8; j++)
                tm = fmaxf(tm, fmaxf(sacc[j][h2 * 2], sacc[j][h2 * 2 + 1]));
            tm = fmaxf(tm, __shfl_xor_sync(0xffffffffu, tm, 1));
            tm = fmaxf(tm, __shfl_xor_sync(0xffffffffu, tm, 2));
            float mnew = fmaxf(mrow[h2], tm);
            float corr = ex2f(mrow[h2] - mnew);
            float sum = 0.f;
            #pragma unroll
            for (int j = 0; j < 8; j++) {
                float p0 = ex2f(sacc[j][h2 * 2] - mnew);
                float p1 = ex2f(sacc[j][h2 * 2 + 1] - mnew);
                sacc[j][h2 * 2] = p0; sacc[j][h2 * 2 + 1] = p1;
                sum += p0 + p1;
            }
            sum += __shfl_xor_sync(0xffffffffu, sum, 1);
            sum += __shfl_xor_sync(0xffffffffu, sum, 2);
            lrow[h2] = lrow[h2] * corr + sum;
            mrow[h2] = mnew;
            #pragma unroll
            for (int jn = 0; jn < 16; jn++) {
                oacc[jn][h2 * 2]     *= corr;
                oacc[jn][h2 * 2 + 1] *= corr;
            }
        }

        // ---- O += P V (3-term); P frags from S accumulators (FA2 identity)
        #pragma unroll
        for (int ks = 0; ks < 4; ks++) {
            uint32_t phi[4], plo[4];
            const int j0 = 2 * ks, j1 = 2 * ks + 1;
            pack_hilo(sacc[j0][0], sacc[j0][1], phi[0], plo[0]);
            pack_hilo(sacc[j0][2], sacc[j0][3], phi[1], plo[1]);
            pack_hilo(sacc[j1][0], sacc[j1][1], phi[2], plo[2]);
            pack_hilo(sacc[j1][2], sacc[j1][3], phi[3], plo[3]);
            #pragma unroll
            for (int np = 0; np < 8; np++) {
                uint32_t vh4[4], vl4[4];
                const int vrow = ks * 16 + (lid & 7) + 8 * ((lid >> 3) & 1);
                const int vcol = np * 16 + 8 * (lid >> 4);
                uint32_t vaddr = vrow * AROWB + vcol * 2;
                ldsm4t(vh4, sVh + vaddr);
                ldsm4t(vl4, sVl + vaddr);
                #pragma unroll
                for (int jj = 0; jj < 2; jj++) {
                    const int jn = 2 * np + jj, q = jj * 2;
                    mma_bf16(oacc[jn], phi, vh4[q], vh4[q + 1]);
                    mma_bf16(oacc[jn], phi, vl4[q], vl4[q + 1]);
                    mma_bf16(oacc[jn], plo, vh4[q], vh4[q + 1]);
                }
            }
        }
        __syncthreads();
    }

    // ---- epilogue: normalize, split hi/lo, store y[b, t, h*128 + d]
    #pragma unroll
    for (int h2 = 0; h2 < 2; h2++) {
        float inv = 1.f / lrow[h2];
        int row_t = qt * 128 + wid * 16 + (lid >> 2) + 8 * h2;
        size_t base = ((size_t)b * T_ + row_t) * C_ + h * HD;
        #pragma unroll
        for (int jn = 0; jn < 16; jn++) {
            int col = jn * 8 + 2 * (lid & 3);
            float v0 = oacc[jn][h2 * 2] * inv;
            float v1 = oacc[jn][h2 * 2 + 1] * inv;
            uint32_t hi, lo;
            pack_hilo(v0, v1, hi, lo);
            *(uint32_t*)(Yhi + base + col) = hi;
            *(uint32_t*)(Ylo + base + col) = lo;
        }
    }
}

// ---------------------------------------------------------------------------
extern "C" void kernel_launch(void* const* d_in, const int* in_sizes, int n_in,
                              void* d_out, int out_size)
{
    const float* x    = (const float*)d_in[0];
    const float* fcos = (const float*)d_in[1];
    const float* fsin = (const float*)d_in[2];
    const float* wq   = (const float*)d_in[3];
    const float* wk   = (const float*)d_in[4];
    const float* wv   = (const float*)d_in[5];
    const float* wo   = (const float*)d_in[6];
    float* out = (float*)d_out;

    float *qp, *kp, *vp;
    cudaGetSymbolAddress((void**)&qp, g_q);
    cudaGetSymbolAddress((void**)&kp, g_k);
    cudaGetSymbolAddress((void**)&vp, g_v);

    __nv_bfloat16 *xhi, *xlo, *yhi, *ylo;
    __nv_bfloat16 *qhi, *qlo, *khi, *klo, *vhi, *vlo;
    __nv_bfloat16 *wqhi, *wqlo, *wkhi, *wklo, *wvhi, *wvlo, *wohi, *wolo;
    cudaGetSymbolAddress((void**)&xhi, g_xhi);   cudaGetSymbolAddress((void**)&xlo, g_xlo);
    cudaGetSymbolAddress((void**)&yhi, g_yhi);   cudaGetSymbolAddress((void**)&ylo, g_ylo);
    cudaGetSymbolAddress((void**)&qhi, g_qhi);   cudaGetSymbolAddress((void**)&qlo, g_qlo);
    cudaGetSymbolAddress((void**)&khi, g_khi);   cudaGetSymbolAddress((void**)&klo, g_klo);
    cudaGetSymbolAddress((void**)&vhi, g_vhi);   cudaGetSymbolAddress((void**)&vlo, g_vlo);
    cudaGetSymbolAddress((void**)&wqhi, g_wqhi); cudaGetSymbolAddress((void**)&wqlo, g_wqlo);
    cudaGetSymbolAddress((void**)&wkhi, g_wkhi); cudaGetSymbolAddress((void**)&wklo, g_wklo);
    cudaGetSymbolAddress((void**)&wvhi, g_wvhi); cudaGetSymbolAddress((void**)&wvlo, g_wvlo);
    cudaGetSymbolAddress((void**)&wohi, g_wohi); cudaGetSymbolAddress((void**)&wolo, g_wolo);

    const int M = B_ * T_;  // 4096

    // fp32 -> bf16 hi/lo splits of inputs/weights
    {
        int n4;
        n4 = (M * C_) / 4;
        cvt_hilo<<<(n4 + 255) / 256, 256>>>((const float4*)x, (__nv_bfloat162*)xhi, (__nv_bfloat162*)xlo, n4);
        n4 = (C_ * C_) / 4;
        cvt_hilo<<<(n4 + 255) / 256, 256>>>((const float4*)wq, (__nv_bfloat162*)wqhi, (__nv_bfloat162*)wqlo, n4);
        cvt_hilo<<<(n4 + 255) / 256, 256>>>((const float4*)wo, (__nv_bfloat162*)wohi, (__nv_bfloat162*)wolo, n4);
        n4 = (NKV * HD * C_) / 4;
        cvt_hilo<<<(n4 + 255) / 256, 256>>>((const float4*)wk, (__nv_bfloat162*)wkhi, (__nv_bfloat162*)wklo, n4);
        cvt_hilo<<<(n4 + 255) / 256, 256>>>((const float4*)wv, (__nv_bfloat162*)wvhi, (__nv_bfloat162*)wvlo, n4);
    }

    cudaFuncSetAttribute(gemm_mma, cudaFuncAttributeMaxDynamicSharedMemorySize, GSM_TOTAL);

    // QKV projections (fp32 scatter into [B, H, T, D])
    gemm_mma<<<dim3(C_ / 128, M / 128), 256, GSM_TOTAL>>>(xhi, xlo, wqhi, wqlo, qp, C_, C_, 1, NH);
    gemm_mma<<<dim3((NKV * HD) / 128, M / 128), 256, GSM_TOTAL>>>(xhi, xlo, wkhi, wklo, kp, C_, NKV * HD, 1, NKV);
    gemm_mma<<<dim3((NKV * HD) / 128, M / 128), 256, GSM_TOTAL>>>(xhi, xlo, wvhi, wvlo, vp, C_, NKV * HD, 1, NKV);

    // RoPE -> bf16 hi/lo (Q pre-scaled by SCALE*log2e for base-2 softmax)
    rope_hilo<<<(B_ * NH  * T_ * 64) / 256, 256>>>(qp, fcos, fsin,
        (__nv_bfloat162*)qhi, (__nv_bfloat162*)qlo, QSCL);
    rope_hilo<<<(B_ * NKV * T_ * 64) / 256, 256>>>(kp, fcos, fsin,
        (__nv_bfloat162*)khi, (__nv_bfloat162*)klo, 1.0f);
    // V -> bf16 hi/lo
    {
        int n4 = (B_ * NKV * T_ * HD) / 4;
        cvt_hilo<<<(n4 + 255) / 256, 256>>>((const float4*)vp, (__nv_bfloat162*)vhi, (__nv_bfloat162*)vlo, n4);
    }

    // Tensor-core flash attention -> yhi/ylo
    cudaFuncSetAttribute(attn_mma, cudaFuncAttributeMaxDynamicSharedMemorySize, ASM_TOTAL);
    attn_mma<<<dim3(T_ / 128, B_ * NH), 256, ASM_TOTAL>>>(qhi, qlo, khi, klo, vhi, vlo, yhi, ylo);

    // Output projection
    gemm_mma<<<dim3(C_ / 128, M / 128), 256, GSM_TOTAL>>>(yhi, ylo, wohi, wolo, out, C_, C_, 0, 0);
}